// round 2
// baseline (speedup 1.0000x reference)
#include <cuda_runtime.h>
#include <cstdint>
#include <cstddef>

// Problem dims
#define T_STEPS 512
#define BATCH   256
#define DIN     128
#define HDIM    256
#define PDIM    128
#define DH      384            // DIN + HDIM

// Decomposition: 32 clusters x 4 CTAs. Each cluster owns 8 batch rows for all T.
// Rank r owns prototypes [r*32, r*32+32) and hidden cols [r*64, r*64+64) of all 4 gates.
#define CLUSTER 4
#define BT      8
#define NTHR    256

// Shared-memory layout (offsets in floats)
#define OFF_PROTO 0                 // [32][384]  rank's prototype slice
#define OFF_WT    12288             // [128][256] WT[p][g*64+hl] = W_g[rank*64+hl][p]
#define OFF_C     45056             // [8][384]   combined [x | h]
#define OFF_KT    48128             // [128][8]   kT[p][b] (full P, all ranks write)
#define OFF_PRE   49152             // [8][256]   gate preactivations (rank's cols)
#define OFF_CX    51200             // [8][64]    cell-state slice (rank-local forever)
#define OFF_BIAS  51712             // [256]
#define OFF_PN    51968             // [32]       ||proto_p||^2
#define OFF_CN    52000             // [8]        ||c_b||^2
#define SMEM_FLOATS 52008
#define SMEM_BYTES  (SMEM_FLOATS * 4)   // 208032 B < 227KB

// ---------------- helpers ----------------

__device__ __forceinline__ uint32_t cvta_shared_u32(const void* p) {
    uint32_t a;
    asm("{ .reg .u64 t; cvta.to.shared.u64 t, %1; cvt.u32.u64 %0, t; }"
        : "=r"(a) : "l"(p));
    return a;
}

// store float into cluster CTA `rank`'s smem at the address corresponding to
// local shared address `saddr`
__device__ __forceinline__ void stc_f32(uint32_t saddr, uint32_t rank, float v) {
    uint32_t ra;
    asm volatile("mapa.shared::cluster.u32 %0, %1, %2;" : "=r"(ra) : "r"(saddr), "r"(rank));
    asm volatile("st.shared::cluster.f32 [%0], %1;" :: "r"(ra), "f"(v) : "memory");
}

__device__ __forceinline__ void cluster_sync_() {
    asm volatile("barrier.cluster.arrive.aligned;" ::: "memory");
    asm volatile("barrier.cluster.wait.aligned;"   ::: "memory");
}

// packed f32x2 (FFMA2 only reachable via PTX)
__device__ __forceinline__ unsigned long long pack2(float lo, float hi) {
    unsigned long long r;
    asm("mov.b64 %0, {%1, %2};" : "=l"(r) : "f"(lo), "f"(hi));
    return r;
}
__device__ __forceinline__ unsigned long long ffma2(unsigned long long a,
                                                    unsigned long long b,
                                                    unsigned long long c) {
    unsigned long long d;
    asm("fma.rn.f32x2 %0, %1, %2, %3;" : "=l"(d) : "l"(a), "l"(b), "l"(c));
    return d;
}
__device__ __forceinline__ void unpack2(unsigned long long v, float& lo, float& hi) {
    asm("mov.b64 {%0, %1}, %2;" : "=f"(lo), "=f"(hi) : "l"(v));
}

__device__ __forceinline__ float sigf(float x) {
    // robust: x -> -inf gives e=inf -> 1/inf = 0; x -> +inf gives e=0 -> 1
    return __fdividef(1.f, 1.f + __expf(-x));
}
__device__ __forceinline__ float tanhf_fast(float x) {
    // abs-form: e in (0,1], no overflow for any x
    float ax = fabsf(x);
    float e  = __expf(-2.f * ax);
    float r  = __fdividef(1.f - e, 1.f + e);
    return copysignf(r, x);
}

// ---------------- kernel ----------------

__global__ void __cluster_dims__(CLUSTER, 1, 1) __launch_bounds__(NTHR, 1)
qlstm_kernel(const float* __restrict__ xin,   const float* __restrict__ proto,
             const float* __restrict__ Wf_p,  const float* __restrict__ bf_p,
             const float* __restrict__ Wi_p,  const float* __restrict__ bi_p,
             const float* __restrict__ Wg_p,  const float* __restrict__ bg_p,
             const float* __restrict__ Wo_p,  const float* __restrict__ bo_p,
             float* __restrict__ out)
{
    extern __shared__ float sm[];
    float* protoS = sm + OFF_PROTO;
    float* WTs    = sm + OFF_WT;
    float* cS     = sm + OFF_C;
    float* kTs    = sm + OFF_KT;
    float* preS   = sm + OFF_PRE;
    float* cxS    = sm + OFF_CX;
    float* biasS  = sm + OFF_BIAS;
    float* pnS    = sm + OFF_PN;
    float* cnS    = sm + OFF_CN;

    const int tid  = threadIdx.x;
    const int lane = tid & 31;
    const int w    = tid >> 5;                  // warp id 0..7
    const int rank = (int)(blockIdx.x & 3);     // == %cluster_ctarank (x-major clusters)
    const int B0   = (int)(blockIdx.x >> 2) * BT;
    const uint32_t smem_u32 = cvta_shared_u32(sm);

    // ---------- one-time init: load constants into smem ----------
    // prototype slice: rank's 32 rows of [P, DH]
    {
        const float* psrc = proto + (size_t)(rank * 32) * DH;
        for (int i = tid; i < 32 * DH; i += NTHR) protoS[i] = psrc[i];
    }
    // weights, transposed into WT[p][g*64+hl]
    {
        const float* Wsrc0 = Wf_p; const float* Wsrc1 = Wi_p;
        const float* Wsrc2 = Wg_p; const float* Wsrc3 = Wo_p;
        #pragma unroll
        for (int g = 0; g < 4; g++) {
            const float* Wg_ = (g == 0) ? Wsrc0 : (g == 1) ? Wsrc1 : (g == 2) ? Wsrc2 : Wsrc3;
            for (int i = tid; i < PDIM * 64; i += NTHR) {
                int hl = i >> 7;           // 0..63
                int p  = i & 127;          // coalesced over p (W row)
                WTs[p * 256 + g * 64 + hl] = Wg_[(size_t)(rank * 64 + hl) * PDIM + p];
            }
        }
    }
    // bias slice
    if (tid < 64) {
        biasS[        tid] = bf_p[rank * 64 + tid];
        biasS[ 64 +   tid] = bi_p[rank * 64 + tid];
        biasS[128 +   tid] = bg_p[rank * 64 + tid];
        biasS[192 +   tid] = bo_p[rank * 64 + tid];
    }
    // zero combined buffer (h part must be 0 at t=0) and cell state
    for (int i = tid; i < BT * DH; i += NTHR) cS[i]  = 0.f;
    for (int i = tid; i < BT * 64; i += NTHR) cxS[i] = 0.f;
    __syncthreads();

    // prototype squared norms
    if (tid < 32) {
        const float4* pr = (const float4*)(protoS + tid * DH);
        float s = 0.f;
        #pragma unroll 8
        for (int q = 0; q < DH / 4; q++) {
            float4 v = pr[q];
            s += v.x * v.x + v.y * v.y + v.z * v.z + v.w * v.w;
        }
        pnS[tid] = s;
    }
    __syncthreads();
    cluster_sync_();   // everyone initialized before DSMEM traffic starts

    // prefetch x for t=0: cluster slice is 8*128 floats = exactly 256 float4
    float4 xreg = ((const float4*)(xin + (size_t)B0 * DIN))[tid];

    for (int t = 0; t < T_STEPS; t++) {
        // ---------- phase A: combined vector + ||c||^2 ----------
        // store x part: thread -> (b = tid>>5, j4 = tid&31)
        ((float4*)(cS + (tid >> 5) * DH))[tid & 31] = xreg;
        if (t + 1 < T_STEPS) {
            xreg = ((const float4*)(xin + (size_t)(t + 1) * BATCH * DIN
                                        + (size_t)B0 * DIN))[tid];
        }
        __syncthreads();
        {
            // warp w computes cn[b=w]
            const float4* cb = (const float4*)(cS + w * DH);
            float4 a0 = cb[lane];
            float4 a1 = cb[32 + lane];
            float4 a2 = cb[64 + lane];
            float s = a0.x * a0.x + a0.y * a0.y + a0.z * a0.z + a0.w * a0.w
                    + a1.x * a1.x + a1.y * a1.y + a1.z * a1.z + a1.w * a1.w
                    + a2.x * a2.x + a2.y * a2.y + a2.z * a2.z + a2.w * a2.w;
            #pragma unroll
            for (int m = 16; m >= 1; m >>= 1)
                s += __shfl_xor_sync(0xffffffffu, s, m);
            if (lane == 0) cnS[w] = s;
        }
        __syncthreads();

        // ---------- phase B: RBF kernel k[b][p] for rank's 32 protos ----------
        {
            const int pp0 = w * 4;          // warp owns 4 local protos
            float acc[32];
            #pragma unroll
            for (int i = 0; i < 32; i++) acc[i] = 0.f;

            #pragma unroll 3
            for (int jc = 0; jc < 12; jc++) {
                const int jj = jc * 32 + lane;
                float cv[8], pv[4];
                #pragma unroll
                for (int b2 = 0; b2 < 8; b2++) cv[b2] = cS[b2 * DH + jj];
                #pragma unroll
                for (int q = 0; q < 4; q++)  pv[q] = protoS[(pp0 + q) * DH + jj];
                #pragma unroll
                for (int b2 = 0; b2 < 8; b2++) {
                    #pragma unroll
                    for (int q = 0; q < 4; q++)
                        acc[b2 * 4 + q] += cv[b2] * pv[q];
                }
            }
            // xor-merge reduce: 31 shfl+add; lane l ends with dot for idx=l
            #pragma unroll
            for (int s5 = 0; s5 < 5; s5++) {
                const int m = 1 << s5;
                const int L = 32 >> s5;
                const bool hi = (lane & m) != 0;
                #pragma unroll
                for (int i = 0; i < (L >> 1); i++) {
                    float mine = hi ? acc[2 * i + 1] : acc[2 * i];
                    float send = hi ? acc[2 * i]     : acc[2 * i + 1];
                    acc[i] = mine + __shfl_xor_sync(0xffffffffu, send, m);
                }
            }
            const int b   = lane >> 2;
            const int ppl = lane & 3;
            const float d2 = cnS[b] + pnS[pp0 + ppl] - 2.f * acc[0];
            const float kv = __expf(-d2);     // GAMMA = 1
            const int  pg  = rank * 32 + pp0 + ppl;
            const uint32_t a = smem_u32 + (uint32_t)(OFF_KT + pg * 8 + b) * 4u;
            stc_f32(a, 0, kv); stc_f32(a, 1, kv); stc_f32(a, 2, kv); stc_f32(a, 3, kv);
        }
        cluster_sync_();   // full kT visible everywhere

        // ---------- phase C: gate GEMM (f32x2) ----------
        {
            const int hc = w * 32 + lane;     // rank-local gate column 0..255
            const float bv = biasS[hc];
            unsigned long long acc0 = pack2(bv, bv);
            unsigned long long acc1 = acc0, acc2 = acc0, acc3 = acc0;

            #pragma unroll 4
            for (int p = 0; p < PDIM; p++) {
                const float4 ka = *(const float4*)(kTs + p * 8);
                const float4 kb = *(const float4*)(kTs + p * 8 + 4);
                const float  wv = WTs[p * 256 + hc];
                const unsigned long long wv2 = pack2(wv, wv);
                acc0 = ffma2(pack2(ka.x, ka.y), wv2, acc0);
                acc1 = ffma2(pack2(ka.z, ka.w), wv2, acc1);
                acc2 = ffma2(pack2(kb.x, kb.y), wv2, acc2);
                acc3 = ffma2(pack2(kb.z, kb.w), wv2, acc3);
            }
            float lo, hi;
            unpack2(acc0, lo, hi); preS[0 * 256 + hc] = lo; preS[1 * 256 + hc] = hi;
            unpack2(acc1, lo, hi); preS[2 * 256 + hc] = lo; preS[3 * 256 + hc] = hi;
            unpack2(acc2, lo, hi); preS[4 * 256 + hc] = lo; preS[5 * 256 + hc] = hi;
            unpack2(acc3, lo, hi); preS[6 * 256 + hc] = lo; preS[7 * 256 + hc] = hi;
        }
        __syncthreads();

        // ---------- gate combine + state update + outputs ----------
        #pragma unroll
        for (int u = 0; u < 2; u++) {
            const int idx = tid + u * NTHR;     // 512 (b,hl) pairs over 256 threads
            const int b  = idx >> 6;
            const int hl = idx & 63;
            const float pf  = preS[b * 256 +       hl];
            const float pi_ = preS[b * 256 +  64 + hl];
            const float pg_ = preS[b * 256 + 128 + hl];
            const float po  = preS[b * 256 + 192 + hl];
            const float f  = sigf(pf);
            const float ii = sigf(pi_);
            const float g  = tanhf_fast(pg_);
            const float oo = sigf(po);
            const float cv = f * cxS[b * 64 + hl] + ii * g;
            cxS[b * 64 + hl] = cv;
            const float h = oo * tanhf_fast(cv);

            const size_t obase = (size_t)t * BATCH * HDIM
                               + (size_t)(B0 + b) * HDIM + rank * 64 + hl;
            out[obase] = h;

            // deliver h slice into every rank's combined buffer for next step
            const uint32_t a = smem_u32
                + (uint32_t)(OFF_C + b * DH + DIN + rank * 64 + hl) * 4u;
            stc_f32(a, 0, h); stc_f32(a, 1, h); stc_f32(a, 2, h); stc_f32(a, 3, h);

            if (t == T_STEPS - 1) {
                const size_t fbase = (size_t)T_STEPS * BATCH * HDIM
                                   + (size_t)(B0 + b) * HDIM + rank * 64 + hl;
                out[fbase] = h;                                  // hx
                out[fbase + (size_t)BATCH * HDIM] = cv;          // cx
            }
        }
        cluster_sync_();   // h deliveries complete before next step's reads
    }
}

extern "C" void kernel_launch(void* const* d_in, const int* in_sizes, int n_in,
                              void* d_out, int out_size) {
    (void)in_sizes; (void)n_in; (void)out_size;
    const float* xin   = (const float*)d_in[0];
    const float* proto = (const float*)d_in[1];
    const float* Wf    = (const float*)d_in[2];
    const float* bf    = (const float*)d_in[3];
    const float* Wi    = (const float*)d_in[4];
    const float* bi    = (const float*)d_in[5];
    const float* Wg    = (const float*)d_in[6];
    const float* bg    = (const float*)d_in[7];
    const float* Wo    = (const float*)d_in[8];
    const float* bo    = (const float*)d_in[9];
    float* out = (float*)d_out;

    cudaFuncSetAttribute(qlstm_kernel,
                         cudaFuncAttributeMaxDynamicSharedMemorySize, SMEM_BYTES);
    qlstm_kernel<<<(BATCH / BT) * CLUSTER, NTHR, SMEM_BYTES>>>(
        xin, proto, Wf, bf, Wi, bi, Wg, bg, Wo, bo, out);
}